// round 3
// baseline (speedup 1.0000x reference)
#include <cuda_runtime.h>
#include <math.h>

#define KEEP 100
#define NCAND 25600
#define NBLK 96
#define NT 1024
#define FULL 0xFFFFFFFFu

struct Params {
    const float* x;
    const float* W[3];
    const float* sw1[3]; const float* sb1[3];
    const float* sw2[3]; const float* sb2[3];
    float* out;
};

// ---------------- device scratch (no allocations) ----------------
__device__ float    gU[3][32][256];          // U_l[h][i] = sum_o sw1[h,o]*W[o,i]
__device__ float    gWt0[256 * 256];         // W0 transposed: gWt0[ip*256+i] = W0[i][ip]
__device__ float    gWt1[256 * 256];
__device__ float    gWt2[256 * 128];         // W2^T: gWt2[i*128+j] = W2[j][i]
__device__ int      gSelIdx[2][16][KEEP];
__device__ float    gSelVal[2][16][KEEP];
__device__ unsigned gKeysA[16][NCAND];
__device__ unsigned gKeysB[16][NCAND];
__device__ unsigned gBarCt[8];
__device__ unsigned gBarGen[8];

struct SM {
    union {
        float sU[256 * 33];                  // padded U: sU[i*33+h]
        float tile[64][65];                  // transpose tile
    } u;
    unsigned hist[256];
    unsigned cum[256];
    int      selI[KEEP];
    float    selS[KEEP];
    int      eq[512];
    int      ip[KEEP];
    float    cv[KEEP];
    float    b1c[32], w2c[32];
    float    wc[KEEP];
    float    red[4];
    int      cnt[4];
};

__device__ __forceinline__ unsigned fkey(float f) {
    unsigned u = __float_as_uint(f);
    return (u & 0x80000000u) ? ~u : (u | 0x80000000u);
}
__device__ __forceinline__ float ikey(unsigned k) {
    return __uint_as_float((k & 0x80000000u) ? (k & 0x7FFFFFFFu) : ~k);
}
__device__ __forceinline__ float ftanh(float x) {
    float e = __expf(2.f * x);               // MUFU.EX2-based, inf-safe
    return 1.f - __fdividef(2.f, e + 1.f);   // e->inf => 1 ; e->0 => -1
}

// ---- software grid barrier: each index used exactly once per launch ----
__device__ __forceinline__ void gridbar(int k) {
    __threadfence();
    __syncthreads();
    if (threadIdx.x == 0) {
        unsigned g = *(volatile unsigned*)&gBarGen[k];
        unsigned old = atomicAdd(&gBarCt[k], 1u);
        if (old == NBLK - 1u) {
            atomicExch(&gBarCt[k], 0u);      // reset for next graph replay
            __threadfence();
            atomicAdd(&gBarGen[k], 1u);
        } else {
            while (*(volatile unsigned*)&gBarGen[k] == g) { __nanosleep(64); }
        }
    }
    __syncthreads();
    __threadfence();
}

// ---- exact top-KEEP radix select; deterministic (index-sorted) output ----
__device__ void topk_select(const unsigned* keys, int n, SM* sm, int tid) {
    unsigned prefix = 0u;
    int r = KEEP;
    int lane = tid & 31;
    #pragma unroll
    for (int shift = 24; shift >= 0; shift -= 8) {
        if (tid < 256) sm->hist[tid] = 0u;
        __syncthreads();
        unsigned pm = (shift == 24) ? 0u : (0xFFFFFFFFu << (shift + 8));
        for (int idx = tid; idx < n; idx += NT) {
            unsigned k = keys[idx];
            bool act = ((k & pm) == prefix);
            unsigned bin = (k >> shift) & 255u;
            unsigned am = __ballot_sync(FULL, act);
            if (act) {                       // warp-aggregated histogram atomics
                unsigned peers = __match_any_sync(am, bin);
                if (lane == __ffs(peers) - 1) atomicAdd(&sm->hist[bin], __popc(peers));
            }
        }
        __syncthreads();
        if (tid < 32) {                      // warp-0 suffix scan over 256 bins
            int base = tid * 8;
            unsigned s[8]; unsigned run = 0u;
            #pragma unroll
            for (int j = 7; j >= 0; j--) { run += sm->hist[base + j]; s[j] = run; }
            unsigned t = run;
            #pragma unroll
            for (int off = 1; off < 32; off <<= 1) {
                unsigned uu = __shfl_down_sync(FULL, t, off);
                if (tid + off < 32) t += uu;
            }
            unsigned above = t - run;
            #pragma unroll
            for (int j = 0; j < 8; j++) sm->cum[base + j] = s[j] + above;
        }
        __syncthreads();
        if (tid < 256) {
            unsigned c  = sm->cum[tid];
            unsigned cn = (tid < 255) ? sm->cum[tid + 1] : 0u;
            if (c >= (unsigned)r && cn < (unsigned)r) {
                sm->cnt[2] = tid;
                sm->cnt[3] = r - (int)cn;
            }
        }
        __syncthreads();
        prefix |= ((unsigned)sm->cnt[2]) << shift;
        r = sm->cnt[3];
        __syncthreads();
    }
    unsigned T = prefix;
    if (tid == 0) { sm->cnt[0] = 0; sm->cnt[1] = 0; }
    __syncthreads();
    for (int idx = tid; idx < n; idx += NT) {
        unsigned k = keys[idx];
        if (k > T)       { int pp = atomicAdd(&sm->cnt[0], 1); sm->selI[pp] = idx; }
        else if (k == T) { int pp = atomicAdd(&sm->cnt[1], 1); if (pp < 512) sm->eq[pp] = idx; }
    }
    __syncthreads();
    if (tid == 0) {                          // ties: smallest indices win
        int G = sm->cnt[0], E = KEEP - G;
        int ne = sm->cnt[1] < 512 ? sm->cnt[1] : 512;
        for (int e = 0; e < E; e++) {
            int bmin = 0x7FFFFFFF, bp = 0;
            for (int q = 0; q < ne; q++) if (sm->eq[q] < bmin) { bmin = sm->eq[q]; bp = q; }
            sm->selI[G + e] = bmin; sm->eq[bp] = 0x7FFFFFFF;
        }
    }
    __syncthreads();
    int myIdx = 0, rank = 0;                 // deterministic order: sort by index
    if (tid < KEEP) {
        myIdx = sm->selI[tid];
        for (int q = 0; q < KEEP; q++) rank += (sm->selI[q] < myIdx) ? 1 : 0;
    }
    __syncthreads();
    if (tid < KEEP) sm->selI[rank] = myIdx;
    __syncthreads();
}

// ---- fused candidate scoring: coalesced Wt gather + SMEM U ----
__device__ void score_stage(const Params& p, SM* sm, unsigned* dstKeys,
                            int l, int prevStage, const float* Wt,
                            int b, int k0, int kn, int tid) {
    const float* Ug = &gU[l][0][0];
    for (int idx = tid; idx < 8192; idx += NT) {
        int h = idx >> 8, i = idx & 255;
        sm->u.sU[i * 33 + h] = Ug[idx];      // coalesced LDG, conflict-free STS
    }
    if (tid < KEEP) {
        sm->ip[tid] = gSelIdx[prevStage][b][tid];
        sm->cv[tid] = gSelVal[prevStage][b][tid];
    }
    if (tid < 32) { sm->b1c[tid] = p.sb1[l][tid]; sm->w2c[tid] = p.sw2[l][tid]; }
    __syncthreads();
    float b2 = p.sb2[l][0];
    int i = tid & 255, grp = tid >> 8;
    const float* Ui = &sm->u.sU[i * 33];
    for (int kk = grp; kk < kn; kk += 4) {
        int k = k0 + kk;
        float v = ftanh(Wt[sm->ip[k] * 256 + i] * sm->cv[k]);  // coalesced
        float acc = 0.f;
        #pragma unroll
        for (int h = 0; h < 32; h++) {
            float t = fmaf(v, Ui[h], sm->b1c[h]);
            acc = fmaf(sm->w2c[h], fmaxf(t, 0.f), acc);
        }
        dstKeys[k * 256 + i] = fkey(acc + b2);                 // coalesced
    }
}

__global__ void __launch_bounds__(NT, 1) kAll(Params p) {
    extern __shared__ unsigned keys[];
    __shared__ SM sm;
    const int tid = threadIdx.x;
    const int g = blockIdx.x;

    // ---------- Phase A: U precompute (blocks 0-23) + transposes (24-63) ----------
    if (g < 24) {
        int l = g >> 3, ic = g & 7;
        int wid = tid >> 5, lane = tid & 31;
        int h = wid;
        int i = ic * 32 + lane;
        const float* W  = p.W[l];
        const float* s1 = p.sw1[l];
        int fo = (l == 2) ? 128 : 256;
        float acc = 0.f;
        for (int oc = 0; oc < fo; oc += 32) {
            float sv = s1[h * fo + oc + lane];                 // coalesced
            #pragma unroll
            for (int j = 0; j < 32; j++) {
                float svj = __shfl_sync(FULL, sv, j);
                acc = fmaf(svj, W[(oc + j) * 256 + i], acc);   // coalesced
            }
        }
        gU[l][h][i] = acc;                                     // coalesced
    } else if (g < 64) {
        const float* src; float* dst; int t, srcld, dstld, ncol;
        if (g < 40)      { src = p.W[0]; dst = gWt0; t = g - 24; srcld = 256; dstld = 256; }
        else if (g < 56) { src = p.W[1]; dst = gWt1; t = g - 40; srcld = 256; dstld = 256; }
        else             { src = p.W[2]; dst = gWt2; t = g - 56; srcld = 256; dstld = 128; }
        ncol = srcld >> 6;
        int tr = t / ncol, tc = t % ncol;
        for (int idx = tid; idx < 4096; idx += NT) {
            int r = idx >> 6, c = idx & 63;
            sm.u.tile[r][c] = src[(tr * 64 + r) * srcld + tc * 64 + c];
        }
        __syncthreads();
        for (int idx = tid; idx < 4096; idx += NT) {
            int r = idx >> 6, c = idx & 63;
            dst[(tc * 64 + r) * dstld + tr * 64 + c] = sm.u.tile[c][r];
        }
    }
    gridbar(0);

    // ---------- Phase B: score0 + select0 (16 blocks) ----------
    if (g < 16) {
        int b = g;
        const float* U0 = &gU[0][0][0];
        for (int idx = tid; idx < 8192; idx += NT) {
            int h = idx >> 8, i = idx & 255;
            sm.u.sU[i * 33 + h] = U0[idx];
        }
        if (tid < 32) { sm.b1c[tid] = p.sb1[0][tid]; sm.w2c[tid] = p.sw2[0][tid]; }
        __syncthreads();
        if (tid < 256) {
            float c = p.x[b * 256 + tid];
            const float* Ui = &sm.u.sU[tid * 33];
            float acc = 0.f;
            #pragma unroll
            for (int h = 0; h < 32; h++) {
                float t = fmaf(c, Ui[h], sm.b1c[h]);
                acc = fmaf(sm.w2c[h], fmaxf(t, 0.f), acc);
            }
            keys[tid] = fkey(acc + p.sb2[0][0]);
        }
        __syncthreads();
        topk_select(keys, 256, &sm, tid);
        if (tid < KEEP) {
            int idx = sm.selI[tid];
            gSelIdx[0][b][tid] = idx;
            gSelVal[0][b][tid] = p.x[b * 256 + idx];
        }
    }
    gridbar(1);

    // ---------- Phase C: stage-1 scoring (96 blocks = 16 b x 6 k-chunks) ----------
    {
        int b = g & 15, chunk = g >> 4;
        int k0 = (chunk < 4) ? chunk * 17 : 68 + (chunk - 4) * 16;
        int kn = (chunk < 4) ? 17 : 16;
        score_stage(p, &sm, gKeysA[b], 1, 0, gWt0, b, k0, kn, tid);
    }
    gridbar(2);

    // ---------- Phase D: select1 (16 blocks) ----------
    if (g < 16) {
        int b = g;
        for (int idx = tid; idx < NCAND; idx += NT) keys[idx] = gKeysA[b][idx];
        __syncthreads();
        topk_select(keys, NCAND, &sm, tid);
        if (tid < KEEP) {
            int cand = sm.selI[tid];
            int k = cand >> 8, i = cand & 255;
            int ip = gSelIdx[0][b][k];
            float cvv = gSelVal[0][b][k];
            gSelIdx[1][b][tid] = i;
            gSelVal[1][b][tid] = ftanh(gWt0[ip * 256 + i] * cvv);
        }
    }
    gridbar(3);

    // ---------- Phase E: stage-2 scoring ----------
    {
        int b = g & 15, chunk = g >> 4;
        int k0 = (chunk < 4) ? chunk * 17 : 68 + (chunk - 4) * 16;
        int kn = (chunk < 4) ? 17 : 16;
        score_stage(p, &sm, gKeysB[b], 2, 1, gWt1, b, k0, kn, tid);
    }
    gridbar(4);

    // ---------- Phase F: select2 + softmax + output (16 blocks) ----------
    if (g < 16) {
        int b = g;
        for (int idx = tid; idx < NCAND; idx += NT) keys[idx] = gKeysB[b][idx];
        __syncthreads();
        topk_select(keys, NCAND, &sm, tid);
        if (tid < KEEP) {
            int cand = sm.selI[tid];
            int k = cand >> 8, i = cand & 255;
            int ip = gSelIdx[1][b][k];
            float cvv = gSelVal[1][b][k];
            sm.wc[tid]   = ftanh(gWt1[ip * 256 + i] * cvv);    // c_q (layer-2 input value)
            sm.selS[tid] = ikey(keys[cand]);                   // exact score
        }
        __syncthreads();
        float s = (tid < KEEP) ? sm.selS[tid] : -INFINITY;
        if (tid < 128) {
            float m = s;
            #pragma unroll
            for (int o = 16; o; o >>= 1) m = fmaxf(m, __shfl_xor_sync(FULL, m, o));
            if ((tid & 31) == 0) sm.red[tid >> 5] = m;
        }
        __syncthreads();
        float mx = fmaxf(fmaxf(sm.red[0], sm.red[1]), fmaxf(sm.red[2], sm.red[3]));
        float e = (tid < KEEP) ? __expf(s - mx) : 0.f;
        __syncthreads();
        if (tid < 128) {
            float z = e;
            #pragma unroll
            for (int o = 16; o; o >>= 1) z += __shfl_xor_sync(FULL, z, o);
            if ((tid & 31) == 0) sm.red[tid >> 5] = z;
        }
        __syncthreads();
        float Z = sm.red[0] + sm.red[1] + sm.red[2] + sm.red[3];
        if (tid < KEEP) sm.wc[tid] = sm.wc[tid] * (e / Z);
        __syncthreads();
        if (tid < 128) {
            float acc = 0.f;
            #pragma unroll 4
            for (int q = 0; q < KEEP; q++)
                acc = fmaf(sm.wc[q], gWt2[(sm.selI[q] & 255) * 128 + tid], acc);  // coalesced
            p.out[b * 128 + tid] = acc;
        }
    }
}

// ---------------------------------------------------------------------------------
extern "C" void kernel_launch(void* const* d_in, const int* in_sizes, int n_in,
                              void* d_out, int out_size) {
    Params p;
    p.x = (const float*)d_in[0];
    if (n_in >= 16 && in_sizes[2] == 65536) {
        for (int l = 0; l < 3; l++) p.W[l] = (const float*)d_in[1 + l];
        for (int l = 0; l < 3; l++) {
            int base = 4 + l * 4;
            p.sw1[l] = (const float*)d_in[base];     p.sb1[l] = (const float*)d_in[base + 1];
            p.sw2[l] = (const float*)d_in[base + 2]; p.sb2[l] = (const float*)d_in[base + 3];
        }
    } else {
        for (int l = 0; l < 3; l++) {
            int base = 1 + l * 5;
            p.W[l]   = (const float*)d_in[base];
            p.sw1[l] = (const float*)d_in[base + 1]; p.sb1[l] = (const float*)d_in[base + 2];
            p.sw2[l] = (const float*)d_in[base + 3]; p.sb2[l] = (const float*)d_in[base + 4];
        }
    }
    p.out = (float*)d_out;

    static int attr_set = 0;
    if (!attr_set) {
        cudaFuncSetAttribute(kAll, cudaFuncAttributeMaxDynamicSharedMemorySize, NCAND * 4);
        attr_set = 1;
    }
    kAll<<<NBLK, NT, NCAND * 4>>>(p);
}

// round 5
// speedup vs baseline: 1.1640x; 1.1640x over previous
#include <cuda_runtime.h>
#include <math.h>

#define KEEP 100
#define NBLK 96
#define NT 1024
#define FULL 0xFFFFFFFFu

struct Params {
    const float* x;
    const float* W[3];
    const float* sw1[3]; const float* sb1[3];
    const float* sw2[3]; const float* sb2[3];
    float* out;
};

// ---------------- device scratch (no allocations) ----------------
__device__ float    gU[3][32][256];          // U_l[h][i] = sum_o sw1[h,o]*W[o,i]
__device__ float    gWt0[256 * 256];         // gWt0[ip*256+i] = W0[i][ip]
__device__ float    gWt1[256 * 256];
__device__ float    gWt2[256 * 128];         // gWt2[i*128+j] = W2[j][i]
__device__ unsigned gPartK[2][16][600];      // per-chunk top-100 keys
__device__ int      gPartI[2][16][600];      // global candidate indices
__device__ float    gPartV[2][16][600];      // candidate values (tanh'd scalars)
__device__ unsigned gBarCt[4];
__device__ unsigned gBarGen[4];

struct SM {
    union {
        float sU[256 * 33];                  // padded U: sU[i*33+h]
        float tile[64][65];                  // transpose tile
    } u;
    unsigned hist[256];
    unsigned cum[256];
    int      selI[KEEP];
    float    selS[KEEP];
    int      eq[512];
    int      ip[KEEP];
    float    cv[KEEP];
    float    b1c[32], w2c[32];
    float    wc[KEEP];
    float    red[4];
    int      cnt[4];
};

__device__ __forceinline__ unsigned fkey(float f) {
    unsigned u = __float_as_uint(f);
    return (u & 0x80000000u) ? ~u : (u | 0x80000000u);
}
__device__ __forceinline__ float ikey(unsigned k) {
    return __uint_as_float((k & 0x80000000u) ? (k & 0x7FFFFFFFu) : ~k);
}
__device__ __forceinline__ float ftanh(float x) {
    float e = __expf(2.f * x);
    return 1.f - __fdividef(2.f, e + 1.f);
}

// ---- software grid barrier (self-resetting across graph replays) ----
__device__ __forceinline__ void gridbar(int k) {
    __threadfence();
    __syncthreads();
    if (threadIdx.x == 0) {
        unsigned g = *(volatile unsigned*)&gBarGen[k];
        unsigned old = atomicAdd(&gBarCt[k], 1u);
        if (old == NBLK - 1u) {
            atomicExch(&gBarCt[k], 0u);
            __threadfence();
            atomicAdd(&gBarGen[k], 1u);
        } else {
            while (*(volatile unsigned*)&gBarGen[k] == g) { __nanosleep(64); }
        }
    }
    __syncthreads();
    __threadfence();
}

// ---- exact top-KEEP radix select from SMEM keys; selI[] = indices sorted asc ----
__device__ void topk_select(const unsigned* keys, int n, SM* sm, int tid) {
    unsigned prefix = 0u;
    int r = KEEP;
    int lane = tid & 31;
    int nIter = (n + NT - 1) / NT;
    #pragma unroll
    for (int shift = 24; shift >= 0; shift -= 8) {
        if (tid < 256) sm->hist[tid] = 0u;
        __syncthreads();
        unsigned pm = (shift == 24) ? 0u : (0xFFFFFFFFu << (shift + 8));
        for (int it = 0; it < nIter; it++) {   // uniform trip count: safe warp ops
            int idx = it * NT + tid;
            unsigned k = (idx < n) ? keys[idx] : 0u;
            bool act = (idx < n) && ((k & pm) == prefix);
            unsigned bin = (k >> shift) & 255u;
            unsigned am = __ballot_sync(FULL, act);
            if (act) {
                unsigned peers = __match_any_sync(am, bin);
                if (lane == __ffs(peers) - 1) atomicAdd(&sm->hist[bin], __popc(peers));
            }
        }
        __syncthreads();
        if (tid < 32) {                        // warp-0 suffix scan over 256 bins
            int base = tid * 8;
            unsigned s[8]; unsigned run = 0u;
            #pragma unroll
            for (int j = 7; j >= 0; j--) { run += sm->hist[base + j]; s[j] = run; }
            unsigned t = run;
            #pragma unroll
            for (int off = 1; off < 32; off <<= 1) {
                unsigned uu = __shfl_down_sync(FULL, t, off);
                if (tid + off < 32) t += uu;
            }
            unsigned above = t - run;
            #pragma unroll
            for (int j = 0; j < 8; j++) sm->cum[base + j] = s[j] + above;
        }
        __syncthreads();
        if (tid < 256) {
            unsigned c  = sm->cum[tid];
            unsigned cn = (tid < 255) ? sm->cum[tid + 1] : 0u;
            if (c >= (unsigned)r && cn < (unsigned)r) {
                sm->cnt[2] = tid;
                sm->cnt[3] = r - (int)cn;
            }
        }
        __syncthreads();
        prefix |= ((unsigned)sm->cnt[2]) << shift;
        r = sm->cnt[3];
        __syncthreads();
    }
    unsigned T = prefix;
    if (tid == 0) { sm->cnt[0] = 0; sm->cnt[1] = 0; }
    __syncthreads();
    for (int idx = tid; idx < n; idx += NT) {
        unsigned k = keys[idx];
        if (k > T)       { int pp = atomicAdd(&sm->cnt[0], 1); sm->selI[pp] = idx; }
        else if (k == T) { int pp = atomicAdd(&sm->cnt[1], 1); if (pp < 512) sm->eq[pp] = idx; }
    }
    __syncthreads();
    if (tid == 0) {                            // ties: smallest indices win
        int G = sm->cnt[0], E = KEEP - G;
        int ne = sm->cnt[1] < 512 ? sm->cnt[1] : 512;
        for (int e = 0; e < E; e++) {
            int bmin = 0x7FFFFFFF, bp = 0;
            for (int q = 0; q < ne; q++) if (sm->eq[q] < bmin) { bmin = sm->eq[q]; bp = q; }
            sm->selI[G + e] = bmin; sm->eq[bp] = 0x7FFFFFFF;
        }
    }
    __syncthreads();
    int myIdx = 0, rank = 0;                   // deterministic: sort by index asc
    if (tid < KEEP) {
        myIdx = sm->selI[tid];
        for (int q = 0; q < KEEP; q++) rank += (sm->selI[q] < myIdx) ? 1 : 0;
    }
    __syncthreads();
    if (tid < KEEP) sm->selI[rank] = myIdx;
    __syncthreads();
}

// ---- load U_l into padded SMEM + scorer consts ----
__device__ __forceinline__ void load_U(const Params& p, SM* sm, int l, int tid) {
    const float* Ug = &gU[l][0][0];
    for (int idx = tid; idx < 8192; idx += NT) {
        int h = idx >> 8, i = idx & 255;
        sm->u.sU[i * 33 + h] = Ug[idx];
    }
    if (tid < 32) { sm->b1c[tid] = p.sb1[l][tid]; sm->w2c[tid] = p.sw2[l][tid]; }
}

// ---- score kn*256 candidates (paths k0..k0+kn-1) into SMEM keys/vals ----
__device__ __forceinline__ void score_chunk(SM* sm, const float* Wt, float b2,
                                            unsigned* skeys, float* svals,
                                            int k0, int kn, int tid) {
    int i = tid & 255, grp = tid >> 8;
    const float* Ui = &sm->u.sU[i * 33];
    for (int kk = grp; kk < kn; kk += 4) {
        int k = k0 + kk;                       // GLOBAL path index (round-4 bugfix)
        float v = ftanh(Wt[sm->ip[k] * 256 + i] * sm->cv[k]);   // coalesced
        float acc = 0.f;
        #pragma unroll
        for (int h = 0; h < 32; h++) {
            float t = fmaf(v, Ui[h], sm->b1c[h]);
            acc = fmaf(sm->w2c[h], fmaxf(t, 0.f), acc);
        }
        int loc = kk * 256 + i;
        skeys[loc] = fkey(acc + b2);
        svals[loc] = v;
    }
}

__global__ void __launch_bounds__(NT, 1) kAll(Params p) {
    extern __shared__ unsigned dyn[];
    unsigned* skeys = dyn;                   // 4352 keys
    float*    svals = (float*)(dyn + 4352);  // 4352 values
    __shared__ SM sm;
    const int tid = threadIdx.x;
    const int g = blockIdx.x;
    const int b = g & 15, chunk = g >> 4;
    const int k0 = (chunk < 4) ? chunk * 17 : 68 + (chunk - 4) * 16;
    const int kn = (chunk < 4) ? 17 : 16;

    // ========== Phase A: U precompute (blocks 0-23) + W transposes (24-63) ==========
    if (g < 24) {
        int l = g >> 3, ic = g & 7;
        int h = tid >> 5, lane = tid & 31;
        int i = ic * 32 + lane;
        const float* W  = p.W[l];
        const float* s1 = p.sw1[l];
        int fo = (l == 2) ? 128 : 256;
        float acc = 0.f;
        for (int oc = 0; oc < fo; oc += 32) {
            float sv = s1[h * fo + oc + lane];
            #pragma unroll
            for (int j = 0; j < 32; j++) {
                float svj = __shfl_sync(FULL, sv, j);
                acc = fmaf(svj, W[(oc + j) * 256 + i], acc);
            }
        }
        gU[l][h][i] = acc;
    } else if (g < 64) {
        const float* src; float* dst; int t, srcld, dstld;
        if (g < 40)      { src = p.W[0]; dst = gWt0; t = g - 24; srcld = 256; dstld = 256; }
        else if (g < 56) { src = p.W[1]; dst = gWt1; t = g - 40; srcld = 256; dstld = 256; }
        else             { src = p.W[2]; dst = gWt2; t = g - 56; srcld = 256; dstld = 128; }
        int ncol = srcld >> 6;
        int tr = t / ncol, tc = t % ncol;
        for (int idx = tid; idx < 4096; idx += NT) {
            int r = idx >> 6, c = idx & 63;
            sm.u.tile[r][c] = src[(tr * 64 + r) * srcld + tc * 64 + c];
        }
        __syncthreads();
        for (int idx = tid; idx < 4096; idx += NT) {
            int r = idx >> 6, c = idx & 63;
            dst[(tc * 64 + r) * dstld + tr * 64 + c] = sm.u.tile[c][r];
        }
    }
    gridbar(0);

    // ========== Phase C (all 96): select0 (redundant) + stage-1 score + local top ==========
    {
        load_U(p, &sm, 0, tid);
        __syncthreads();
        if (tid < 256) {                     // score the 256 layer-0 candidates
            float c = p.x[b * 256 + tid];
            const float* Ui = &sm.u.sU[tid * 33];
            float acc = 0.f;
            #pragma unroll
            for (int h = 0; h < 32; h++) {
                float t = fmaf(c, Ui[h], sm.b1c[h]);
                acc = fmaf(sm.w2c[h], fmaxf(t, 0.f), acc);
            }
            skeys[tid] = fkey(acc + p.sb2[0][0]);
        }
        __syncthreads();
        topk_select(skeys, 256, &sm, tid);
        if (tid < KEEP) {
            int i0 = sm.selI[tid];
            sm.ip[tid] = i0;
            sm.cv[tid] = p.x[b * 256 + i0];
        }
        __syncthreads();
        load_U(p, &sm, 1, tid);              // overwrite U0 with U1
        __syncthreads();
        score_chunk(&sm, gWt0, p.sb2[1][0], skeys, svals, k0, kn, tid);
        __syncthreads();
        topk_select(skeys, kn * 256, &sm, tid);
        if (tid < KEEP) {
            int j = sm.selI[tid];
            int slot = chunk * 100 + tid;
            gPartK[0][b][slot] = skeys[j];
            gPartI[0][b][slot] = k0 * 256 + j;
            gPartV[0][b][slot] = svals[j];
        }
    }
    gridbar(1);

    // ========== Phase E (all 96): merge sel1 (redundant) + stage-2 score + local top ==========
    {
        if (tid < 600) skeys[tid] = gPartK[0][b][tid];
        __syncthreads();
        topk_select(skeys, 600, &sm, tid);
        if (tid < KEEP) {
            int j = sm.selI[tid];
            sm.ip[tid] = gPartI[0][b][j] & 255;   // feature index of stage-1 winner
            sm.cv[tid] = gPartV[0][b][j];         // its tanh'd scalar value
        }
        __syncthreads();
        load_U(p, &sm, 2, tid);
        __syncthreads();
        score_chunk(&sm, gWt1, p.sb2[2][0], skeys, svals, k0, kn, tid);
        __syncthreads();
        topk_select(skeys, kn * 256, &sm, tid);
        if (tid < KEEP) {
            int j = sm.selI[tid];
            int slot = chunk * 100 + tid;
            gPartK[1][b][slot] = skeys[j];
            gPartI[1][b][slot] = k0 * 256 + j;
            gPartV[1][b][slot] = svals[j];
        }
    }
    gridbar(2);

    // ========== Phase F (16 blocks): final merge + softmax + output ==========
    if (g < 16) {
        if (tid < 600) skeys[tid] = gPartK[1][b][tid];
        __syncthreads();
        topk_select(skeys, 600, &sm, tid);
        if (tid < KEEP) {
            int j = sm.selI[tid];
            sm.ip[tid]   = gPartI[1][b][j] & 255;
            sm.wc[tid]   = gPartV[1][b][j];       // candidate value (no tanh after L2)
            sm.selS[tid] = ikey(skeys[j]);        // exact selection score
        }
        __syncthreads();
        float s = (tid < KEEP) ? sm.selS[tid] : -INFINITY;
        if (tid < 128) {
            float m = s;
            #pragma unroll
            for (int o = 16; o; o >>= 1) m = fmaxf(m, __shfl_xor_sync(FULL, m, o));
            if ((tid & 31) == 0) sm.red[tid >> 5] = m;
        }
        __syncthreads();
        float mx = fmaxf(fmaxf(sm.red[0], sm.red[1]), fmaxf(sm.red[2], sm.red[3]));
        float e = (tid < KEEP) ? __expf(s - mx) : 0.f;
        __syncthreads();
        if (tid < 128) {
            float z = e;
            #pragma unroll
            for (int o = 16; o; o >>= 1) z += __shfl_xor_sync(FULL, z, o);
            if ((tid & 31) == 0) sm.red[tid >> 5] = z;
        }
        __syncthreads();
        float Z = sm.red[0] + sm.red[1] + sm.red[2] + sm.red[3];
        if (tid < KEEP) sm.wc[tid] = sm.wc[tid] * (e / Z);
        __syncthreads();
        if (tid < 128) {
            float acc = 0.f;
            #pragma unroll 4
            for (int q = 0; q < KEEP; q++)
                acc = fmaf(sm.wc[q], gWt2[sm.ip[q] * 128 + tid], acc);  // coalesced
            p.out[b * 128 + tid] = acc;
        }
    }
}

// ---------------------------------------------------------------------------------
extern "C" void kernel_launch(void* const* d_in, const int* in_sizes, int n_in,
                              void* d_out, int out_size) {
    Params p;
    p.x = (const float*)d_in[0];
    if (n_in >= 16 && in_sizes[2] == 65536) {
        for (int l = 0; l < 3; l++) p.W[l] = (const float*)d_in[1 + l];
        for (int l = 0; l < 3; l++) {
            int base = 4 + l * 4;
            p.sw1[l] = (const float*)d_in[base];     p.sb1[l] = (const float*)d_in[base + 1];
            p.sw2[l] = (const float*)d_in[base + 2]; p.sb2[l] = (const float*)d_in[base + 3];
        }
    } else {
        for (int l = 0; l < 3; l++) {
            int base = 1 + l * 5;
            p.W[l]   = (const float*)d_in[base];
            p.sw1[l] = (const float*)d_in[base + 1]; p.sb1[l] = (const float*)d_in[base + 2];
            p.sw2[l] = (const float*)d_in[base + 3]; p.sb2[l] = (const float*)d_in[base + 4];
        }
    }
    p.out = (float*)d_out;

    const int dynBytes = 4352 * 2 * 4;
    static int attr_set = 0;
    if (!attr_set) {
        cudaFuncSetAttribute(kAll, cudaFuncAttributeMaxDynamicSharedMemorySize, dynBytes);
        attr_set = 1;
    }
    kAll<<<NBLK, NT, dynBytes>>>(p);
}

// round 6
// speedup vs baseline: 1.1981x; 1.0293x over previous
#include <cuda_runtime.h>
#include <math.h>

#define KEEP 100
#define NBLK 288
#define NT 256
#define NCHUNK 18
#define MERGEW (NCHUNK * KEEP)   // 1800
#define FULL 0xFFFFFFFFu

struct Params {
    const float* x;
    const float* W[3];
    const float* sw1[3]; const float* sb1[3];
    const float* sw2[3]; const float* sb2[3];
    float* out;
};

// ---------------- device scratch (no allocations) ----------------
__device__ float    gU[3][32][256];          // U_l[h][i]
__device__ float    gWt0[256 * 256];         // gWt0[ip*256+i] = W0[i][ip]
__device__ float    gWt1[256 * 256];
__device__ float    gWt2[256 * 128];         // gWt2[i*128+j] = W2[j][i]
__device__ unsigned gPartK[2][16][MERGEW];
__device__ int      gPartI[2][16][MERGEW];
__device__ float    gPartV[2][16][MERGEW];
__device__ unsigned gBarCt[4];
__device__ unsigned gBarGen[4];

struct SM {
    float    tile[64][65];                   // phase-A transpose only
    unsigned hist[256];
    int      selI[KEEP];
    float    selS[KEEP];
    int      eq[256];
    int      ip[KEEP];
    float    cv[KEEP];
    float    b1c[32], w2c[32];
    float    wc[KEEP];
    float    red[4];
    int      cnt[4];                         // 0:G 1:E 2:byte 3:newr
};

__device__ __forceinline__ unsigned fkey(float f) {
    unsigned u = __float_as_uint(f);
    return (u & 0x80000000u) ? ~u : (u | 0x80000000u);
}
__device__ __forceinline__ float ikey(unsigned k) {
    return __uint_as_float((k & 0x80000000u) ? (k & 0x7FFFFFFFu) : ~k);
}
__device__ __forceinline__ float ftanh(float x) {
    float e = __expf(2.f * x);
    return 1.f - __fdividef(2.f, e + 1.f);
}

// ---- software grid barrier (self-resetting across graph replays) ----
__device__ __forceinline__ void gridbar(int k) {
    __threadfence();
    __syncthreads();
    if (threadIdx.x == 0) {
        unsigned g = *(volatile unsigned*)&gBarGen[k];
        unsigned old = atomicAdd(&gBarCt[k], 1u);
        if (old == NBLK - 1u) {
            atomicExch(&gBarCt[k], 0u);
            __threadfence();
            atomicAdd(&gBarGen[k], 1u);
        } else {
            while (*(volatile unsigned*)&gBarGen[k] == g) { __nanosleep(64); }
        }
    }
    __syncthreads();
    __threadfence();
}

// ---- exact top-KEEP radix select (3 syncs/pass); selI[] sorted ascending ----
__device__ void topk_select(const unsigned* keys, int n, SM* sm, int tid) {
    unsigned prefix = 0u;
    int r = KEEP;
    const int lane = tid & 31, wid = tid >> 5;
    const int nIter = (n + NT - 1) / NT;
    #pragma unroll
    for (int shift = 24; shift >= 0; shift -= 8) {
        sm->hist[tid] = 0u;
        __syncthreads();
        unsigned pm = (shift == 24) ? 0u : (0xFFFFFFFFu << (shift + 8));
        for (int it = 0; it < nIter; it++) {
            int idx = it * NT + tid;
            unsigned k = (idx < n) ? keys[idx] : 0u;
            bool act = (idx < n) && ((k & pm) == prefix);
            unsigned bin = (k >> shift) & 255u;
            unsigned am = __ballot_sync(FULL, act);
            if (act) {
                unsigned peers = __match_any_sync(am, bin);
                if (lane == __ffs(peers) - 1) atomicAdd(&sm->hist[bin], __popc(peers));
            }
        }
        __syncthreads();
        if (wid == 0) {                      // scan + threshold find, warp 0 only
            int base = lane * 8;
            unsigned s[8]; unsigned run = 0u;
            #pragma unroll
            for (int j = 7; j >= 0; j--) { run += sm->hist[base + j]; s[j] = run; }
            unsigned t = run;
            #pragma unroll
            for (int off = 1; off < 32; off <<= 1) {
                unsigned uu = __shfl_down_sync(FULL, t, off);
                if (lane + off < 32) t += uu;
            }
            unsigned above = t - run;        // suffix over lanes > lane
            unsigned cum0 = s[0] + above;
            unsigned nxt7 = __shfl_down_sync(FULL, cum0, 1);
            if (lane == 31) nxt7 = 0u;
            #pragma unroll
            for (int j = 0; j < 8; j++) {
                unsigned cj = s[j] + above;
                unsigned nj = (j < 7) ? (s[j + 1] + above) : nxt7;
                if (cj >= (unsigned)r && nj < (unsigned)r) {
                    sm->cnt[2] = base + j;
                    sm->cnt[3] = r - (int)nj;
                }
            }
        }
        __syncthreads();
        prefix |= ((unsigned)sm->cnt[2]) << shift;
        r = sm->cnt[3];
    }
    unsigned T = prefix;
    if (tid == 0) { sm->cnt[0] = 0; sm->cnt[1] = 0; }
    __syncthreads();
    for (int idx = tid; idx < n; idx += NT) {
        unsigned k = keys[idx];
        if (k > T)       { int pp = atomicAdd(&sm->cnt[0], 1); sm->selI[pp] = idx; }
        else if (k == T) { int pp = atomicAdd(&sm->cnt[1], 1); if (pp < 256) sm->eq[pp] = idx; }
    }
    __syncthreads();
    if (tid == 0) {                          // ties: smallest indices win
        int G = sm->cnt[0], E = KEEP - G;
        int ne = sm->cnt[1] < 256 ? sm->cnt[1] : 256;
        for (int e = 0; e < E; e++) {
            int bmin = 0x7FFFFFFF, bp = 0;
            for (int q = 0; q < ne; q++) if (sm->eq[q] < bmin) { bmin = sm->eq[q]; bp = q; }
            sm->selI[G + e] = bmin; sm->eq[bp] = 0x7FFFFFFF;
        }
    }
    __syncthreads();
    int myIdx = 0, rank = 0;                 // deterministic: sort by index asc
    if (tid < KEEP) {
        myIdx = sm->selI[tid];
        for (int q = 0; q < KEEP; q++) rank += (sm->selI[q] < myIdx) ? 1 : 0;
    }
    __syncthreads();
    if (tid < KEEP) sm->selI[rank] = myIdx;
    __syncthreads();
}

__global__ void __launch_bounds__(NT, 3) kAll(Params p) {
    extern __shared__ unsigned dyn[];
    unsigned* skeys = dyn;                   // MERGEW keys (scoring uses first 1536)
    float*    svals = (float*)(dyn + MERGEW);// 1536 values
    __shared__ SM sm;
    const int tid = threadIdx.x;
    const int g = blockIdx.x;
    const int b = g & 15, chunk = g >> 4;    // chunk in 0..17
    const int kn = (chunk < 10) ? 6 : 5;
    const int k0 = (chunk < 10) ? chunk * 6 : 60 + (chunk - 10) * 5;
    const int i = tid;                       // feature index owned by this thread
    const int lane = tid & 31;
    float Ureg[32];

    // ========== Phase A: U precompute (blocks 0-23) + W transposes (24-63) ==========
    if (g < 24) {
        int l = g >> 3, ic = g & 7;
        int ii = ic * 32 + lane;
        const float* W  = p.W[l];
        const float* s1 = p.sw1[l];
        int fo = (l == 2) ? 128 : 256;
        for (int hh = 0; hh < 4; hh++) {
            int h = (tid >> 5) + hh * 8;
            float acc = 0.f;
            for (int oc = 0; oc < fo; oc += 32) {
                float sv = s1[h * fo + oc + lane];
                #pragma unroll
                for (int j = 0; j < 32; j++) {
                    float svj = __shfl_sync(FULL, sv, j);
                    acc = fmaf(svj, W[(oc + j) * 256 + ii], acc);
                }
            }
            gU[l][h][ii] = acc;
        }
    } else if (g < 64) {
        const float* src; float* dst; int t, srcld, dstld;
        if (g < 40)      { src = p.W[0]; dst = gWt0; t = g - 24; srcld = 256; dstld = 256; }
        else if (g < 56) { src = p.W[1]; dst = gWt1; t = g - 40; srcld = 256; dstld = 256; }
        else             { src = p.W[2]; dst = gWt2; t = g - 56; srcld = 256; dstld = 128; }
        int ncol = srcld >> 6;
        int tr = t / ncol, tc = t % ncol;
        for (int idx = tid; idx < 4096; idx += NT) {
            int r = idx >> 6, c = idx & 63;
            sm.tile[r][c] = src[(tr * 64 + r) * srcld + tc * 64 + c];
        }
        __syncthreads();
        for (int idx = tid; idx < 4096; idx += NT) {
            int r = idx >> 6, c = idx & 63;
            dst[(tc * 64 + r) * dstld + tr * 64 + c] = sm.tile[c][r];
        }
    }
    gridbar(0);

    // ========== Phase B: select0 (redundant) + stage-1 chunk score + local top ==========
    {
        #pragma unroll
        for (int h = 0; h < 32; h++) Ureg[h] = gU[0][h][i];    // coalesced per h
        if (tid < 32) { sm.b1c[tid] = p.sb1[0][tid]; sm.w2c[tid] = p.sw2[0][tid]; }
        __syncthreads();
        float c = p.x[b * 256 + i];
        float acc = 0.f;
        #pragma unroll
        for (int h = 0; h < 32; h++) {
            float t = fmaf(c, Ureg[h], sm.b1c[h]);
            acc = fmaf(sm.w2c[h], fmaxf(t, 0.f), acc);
        }
        skeys[i] = fkey(acc + p.sb2[0][0]);
        __syncthreads();
        topk_select(skeys, 256, &sm, tid);
        if (tid < KEEP) {
            int i0 = sm.selI[tid];
            sm.ip[tid] = i0;
            sm.cv[tid] = p.x[b * 256 + i0];
        }
        #pragma unroll
        for (int h = 0; h < 32; h++) Ureg[h] = gU[1][h][i];
        if (tid < 32) { sm.b1c[tid] = p.sb1[1][tid]; sm.w2c[tid] = p.sw2[1][tid]; }
        __syncthreads();
        float b2 = p.sb2[1][0];
        for (int kk = 0; kk < kn; kk++) {
            int k = k0 + kk;
            float v = ftanh(gWt0[sm.ip[k] * 256 + i] * sm.cv[k]);   // coalesced
            float a2 = 0.f;
            #pragma unroll
            for (int h = 0; h < 32; h++) {
                float t = fmaf(v, Ureg[h], sm.b1c[h]);
                a2 = fmaf(sm.w2c[h], fmaxf(t, 0.f), a2);
            }
            skeys[kk * 256 + i] = fkey(a2 + b2);
            svals[kk * 256 + i] = v;
        }
        __syncthreads();
        topk_select(skeys, kn * 256, &sm, tid);
        if (tid < KEEP) {
            int j = sm.selI[tid];
            int slot = chunk * KEEP + tid;
            gPartK[0][b][slot] = skeys[j];
            gPartI[0][b][slot] = k0 * 256 + j;
            gPartV[0][b][slot] = svals[j];
        }
    }
    gridbar(1);

    // ========== Phase C: merge sel1 (redundant) + stage-2 chunk score + local top ==========
    {
        for (int idx = tid; idx < MERGEW; idx += NT) skeys[idx] = gPartK[0][b][idx];
        __syncthreads();
        topk_select(skeys, MERGEW, &sm, tid);
        if (tid < KEEP) {
            int j = sm.selI[tid];
            sm.ip[tid] = gPartI[0][b][j] & 255;
            sm.cv[tid] = gPartV[0][b][j];
        }
        #pragma unroll
        for (int h = 0; h < 32; h++) Ureg[h] = gU[2][h][i];
        if (tid < 32) { sm.b1c[tid] = p.sb1[2][tid]; sm.w2c[tid] = p.sw2[2][tid]; }
        __syncthreads();
        float b2 = p.sb2[2][0];
        for (int kk = 0; kk < kn; kk++) {
            int k = k0 + kk;
            float v = ftanh(gWt1[sm.ip[k] * 256 + i] * sm.cv[k]);
            float a2 = 0.f;
            #pragma unroll
            for (int h = 0; h < 32; h++) {
                float t = fmaf(v, Ureg[h], sm.b1c[h]);
                a2 = fmaf(sm.w2c[h], fmaxf(t, 0.f), a2);
            }
            skeys[kk * 256 + i] = fkey(a2 + b2);
            svals[kk * 256 + i] = v;
        }
        __syncthreads();
        topk_select(skeys, kn * 256, &sm, tid);
        if (tid < KEEP) {
            int j = sm.selI[tid];
            int slot = chunk * KEEP + tid;
            gPartK[1][b][slot] = skeys[j];
            gPartI[1][b][slot] = k0 * 256 + j;
            gPartV[1][b][slot] = svals[j];
        }
    }
    gridbar(2);

    // ========== Phase D (16 blocks): final merge + softmax + output ==========
    if (g < 16) {
        for (int idx = tid; idx < MERGEW; idx += NT) skeys[idx] = gPartK[1][b][idx];
        __syncthreads();
        topk_select(skeys, MERGEW, &sm, tid);
        if (tid < KEEP) {
            int j = sm.selI[tid];
            sm.ip[tid]   = gPartI[1][b][j] & 255;
            sm.wc[tid]   = gPartV[1][b][j];       // value (no tanh after last layer)
            sm.selS[tid] = ikey(skeys[j]);        // exact selection score
        }
        __syncthreads();
        float s = (tid < KEEP) ? sm.selS[tid] : -INFINITY;
        if (tid < 128) {
            float m = s;
            #pragma unroll
            for (int o = 16; o; o >>= 1) m = fmaxf(m, __shfl_xor_sync(FULL, m, o));
            if (lane == 0) sm.red[tid >> 5] = m;
        }
        __syncthreads();
        float mx = fmaxf(fmaxf(sm.red[0], sm.red[1]), fmaxf(sm.red[2], sm.red[3]));
        float e = (tid < KEEP) ? __expf(s - mx) : 0.f;
        __syncthreads();
        if (tid < 128) {
            float z = e;
            #pragma unroll
            for (int o = 16; o; o >>= 1) z += __shfl_xor_sync(FULL, z, o);
            if (lane == 0) sm.red[tid >> 5] = z;
        }
        __syncthreads();
        float Z = sm.red[0] + sm.red[1] + sm.red[2] + sm.red[3];
        if (tid < KEEP) sm.wc[tid] = sm.wc[tid] * (e / Z);
        __syncthreads();
        if (tid < 128) {
            float acc = 0.f;
            #pragma unroll 4
            for (int q = 0; q < KEEP; q++)
                acc = fmaf(sm.wc[q], gWt2[sm.ip[q] * 128 + tid], acc);  // coalesced
            p.out[b * 128 + tid] = acc;
        }
    }
}

// ---------------------------------------------------------------------------------
extern "C" void kernel_launch(void* const* d_in, const int* in_sizes, int n_in,
                              void* d_out, int out_size) {
    Params p;
    p.x = (const float*)d_in[0];
    if (n_in >= 16 && in_sizes[2] == 65536) {
        for (int l = 0; l < 3; l++) p.W[l] = (const float*)d_in[1 + l];
        for (int l = 0; l < 3; l++) {
            int base = 4 + l * 4;
            p.sw1[l] = (const float*)d_in[base];     p.sb1[l] = (const float*)d_in[base + 1];
            p.sw2[l] = (const float*)d_in[base + 2]; p.sb2[l] = (const float*)d_in[base + 3];
        }
    } else {
        for (int l = 0; l < 3; l++) {
            int base = 1 + l * 5;
            p.W[l]   = (const float*)d_in[base];
            p.sw1[l] = (const float*)d_in[base + 1]; p.sb1[l] = (const float*)d_in[base + 2];
            p.sw2[l] = (const float*)d_in[base + 3]; p.sb2[l] = (const float*)d_in[base + 4];
        }
    }
    p.out = (float*)d_out;

    const int dynBytes = (MERGEW + 1536) * 4;   // keys + values
    kAll<<<NBLK, NT, dynBytes>>>(p);
}

// round 7
// speedup vs baseline: 1.7687x; 1.4763x over previous
#include <cuda_runtime.h>
#include <math.h>

#define KEEP 100
#define NCHUNK 18
#define MERGEW 1800
#define FULL 0xFFFFFFFFu

// ---------------- device scratch (no allocations) ----------------
__device__ float    gU[3][32][256];          // U_l[h][i] = sum_o sw1[h,o]*W_l[o,i]
__device__ float    gWt0[256 * 256];         // gWt0[ip*256+i] = W0[i][ip]
__device__ float    gWt1[256 * 256];
__device__ float    gWt2[256 * 128];         // gWt2[i*128+j] = W2[j][i]
__device__ int      gSelIdx[2][16][KEEP];    // kept-path feature index
__device__ float    gSelVal[2][16][KEEP];    // kept-path scalar value
__device__ unsigned gPartK[2][16][MERGEW];   // per-chunk top-100 keys
__device__ int      gPartI[2][16][MERGEW];   // local candidate ids
__device__ float    gPartV[2][16][MERGEW];   // candidate values

struct TK {                                   // select scratch (shared)
    unsigned hist[256];
    int      selI[KEEP];
    int      eq[256];
    int      cnt[4];                          // 0:G 1:E 2:byte 3:newr
};

__device__ __forceinline__ unsigned fkey(float f) {
    unsigned u = __float_as_uint(f);
    return (u & 0x80000000u) ? ~u : (u | 0x80000000u);
}
__device__ __forceinline__ float ikey(unsigned k) {
    return __uint_as_float((k & 0x80000000u) ? (k & 0x7FFFFFFFu) : ~k);
}
__device__ __forceinline__ float ftanh(float x) {
    float e = __expf(2.f * x);
    return 1.f - __fdividef(2.f, e + 1.f);
}

// ---- exact top-KEEP radix select; selI[] = selected indices sorted ascending ----
__device__ void topk(const unsigned* keys, int n, TK* t, int tid, int nt) {
    unsigned prefix = 0u;
    int r = KEEP;
    const int lane = tid & 31;
    const int nIter = (n + nt - 1) / nt;
    #pragma unroll
    for (int shift = 24; shift >= 0; shift -= 8) {
        if (tid < 256) t->hist[tid] = 0u;
        __syncthreads();
        unsigned pm = (shift == 24) ? 0u : (0xFFFFFFFFu << (shift + 8));
        for (int it = 0; it < nIter; it++) {
            int idx = it * nt + tid;
            unsigned k = (idx < n) ? keys[idx] : 0u;
            bool act = (idx < n) && ((k & pm) == prefix);
            unsigned bin = (k >> shift) & 255u;
            unsigned am = __ballot_sync(FULL, act);
            if (act) {
                unsigned peers = __match_any_sync(am, bin);
                if (lane == __ffs(peers) - 1) atomicAdd(&t->hist[bin], __popc(peers));
            }
        }
        __syncthreads();
        if (tid < 32) {                      // warp-0: suffix scan + threshold find
            int base = lane * 8;
            unsigned s[8]; unsigned run = 0u;
            #pragma unroll
            for (int j = 7; j >= 0; j--) { run += t->hist[base + j]; s[j] = run; }
            unsigned tt = run;
            #pragma unroll
            for (int off = 1; off < 32; off <<= 1) {
                unsigned uu = __shfl_down_sync(FULL, tt, off);
                if (lane + off < 32) tt += uu;
            }
            unsigned above = tt - run;
            unsigned cum0 = s[0] + above;
            unsigned nxt7 = __shfl_down_sync(FULL, cum0, 1);
            if (lane == 31) nxt7 = 0u;
            #pragma unroll
            for (int j = 0; j < 8; j++) {
                unsigned cj = s[j] + above;
                unsigned nj = (j < 7) ? (s[j + 1] + above) : nxt7;
                if (cj >= (unsigned)r && nj < (unsigned)r) {
                    t->cnt[2] = base + j;
                    t->cnt[3] = r - (int)nj;
                }
            }
        }
        __syncthreads();
        prefix |= ((unsigned)t->cnt[2]) << shift;
        r = t->cnt[3];
    }
    unsigned T = prefix;
    if (tid == 0) { t->cnt[0] = 0; t->cnt[1] = 0; }
    __syncthreads();
    for (int idx = tid; idx < n; idx += nt) {
        unsigned k = keys[idx];
        if (k > T)       { int pp = atomicAdd(&t->cnt[0], 1); t->selI[pp] = idx; }
        else if (k == T) { int pp = atomicAdd(&t->cnt[1], 1); if (pp < 256) t->eq[pp] = idx; }
    }
    __syncthreads();
    if (tid == 0) {                          // ties: smallest indices win
        int G = t->cnt[0], E = KEEP - G;
        int ne = t->cnt[1] < 256 ? t->cnt[1] : 256;
        for (int e = 0; e < E; e++) {
            int bmin = 0x7FFFFFFF, bp = 0;
            for (int q = 0; q < ne; q++) if (t->eq[q] < bmin) { bmin = t->eq[q]; bp = q; }
            t->selI[G + e] = bmin; t->eq[bp] = 0x7FFFFFFF;
        }
    }
    __syncthreads();
    int myIdx = 0, rank = 0;                 // deterministic: sort by index asc
    if (tid < KEEP) {
        myIdx = t->selI[tid];
        for (int q = 0; q < KEEP; q++) rank += (t->selI[q] < myIdx) ? 1 : 0;
    }
    __syncthreads();
    if (tid < KEEP) t->selI[rank] = myIdx;
    __syncthreads();
}

// ========== k1: U precompute (blocks 0-23) + W transposes (24-63) ==========
__global__ void __launch_bounds__(256) kPrep(const float* __restrict__ W0,
                                             const float* __restrict__ W1,
                                             const float* __restrict__ W2,
                                             const float* __restrict__ s10,
                                             const float* __restrict__ s11,
                                             const float* __restrict__ s12) {
    __shared__ float tile[64][65];
    const int tid = threadIdx.x, g = blockIdx.x;
    const int lane = tid & 31;
    if (g < 24) {
        int l = g >> 3, ic = g & 7;
        int ii = ic * 32 + lane;
        const float* W  = (l == 0) ? W0 : (l == 1) ? W1 : W2;
        const float* s1 = (l == 0) ? s10 : (l == 1) ? s11 : s12;
        int fo = (l == 2) ? 128 : 256;
        for (int hh = 0; hh < 4; hh++) {
            int h = (tid >> 5) + hh * 8;
            float acc = 0.f;
            for (int oc = 0; oc < fo; oc += 32) {
                float sv = s1[h * fo + oc + lane];
                #pragma unroll
                for (int j = 0; j < 32; j++) {
                    float svj = __shfl_sync(FULL, sv, j);
                    acc = fmaf(svj, W[(oc + j) * 256 + ii], acc);
                }
            }
            gU[l][h][ii] = acc;
        }
    } else {
        const float* src; float* dst; int t, srcld, dstld;
        if (g < 40)      { src = W0; dst = gWt0; t = g - 24; srcld = 256; dstld = 256; }
        else if (g < 56) { src = W1; dst = gWt1; t = g - 40; srcld = 256; dstld = 256; }
        else             { src = W2; dst = gWt2; t = g - 56; srcld = 256; dstld = 128; }
        int ncol = srcld >> 6;
        int tr = t / ncol, tc = t % ncol;
        for (int idx = tid; idx < 4096; idx += 256) {
            int r = idx >> 6, c = idx & 63;
            tile[r][c] = src[(tr * 64 + r) * srcld + tc * 64 + c];
        }
        __syncthreads();
        for (int idx = tid; idx < 4096; idx += 256) {
            int r = idx >> 6, c = idx & 63;
            dst[(tc * 64 + r) * dstld + tr * 64 + c] = tile[c][r];
        }
    }
}

// ========== k2: score 256 layer-0 candidates + select top-100 (16 blocks) ==========
__global__ void __launch_bounds__(256) kSel0(const float* __restrict__ x,
                                             const float* __restrict__ sb1,
                                             const float* __restrict__ sw2,
                                             const float* __restrict__ sb2) {
    __shared__ unsigned skeys[256];
    __shared__ TK tk;
    __shared__ float b1c[32], w2c[32];
    const int b = blockIdx.x, tid = threadIdx.x;
    if (tid < 32) { b1c[tid] = sb1[tid]; w2c[tid] = sw2[tid]; }
    float Ureg[32];
    #pragma unroll
    for (int h = 0; h < 32; h++) Ureg[h] = gU[0][h][tid];   // coalesced
    __syncthreads();
    float c = x[b * 256 + tid];
    float acc = 0.f;
    #pragma unroll
    for (int h = 0; h < 32; h++) {
        float t = fmaf(c, Ureg[h], b1c[h]);
        acc = fmaf(w2c[h], fmaxf(t, 0.f), acc);
    }
    skeys[tid] = fkey(acc + sb2[0]);
    __syncthreads();
    topk(skeys, 256, &tk, tid, 256);
    if (tid < KEEP) {
        int i0 = tk.selI[tid];
        gSelIdx[0][b][tid] = i0;
        gSelVal[0][b][tid] = x[b * 256 + i0];
    }
}

// ========== k3/k5: score one chunk's candidates + local top-100 (288 blocks) ==========
__global__ void __launch_bounds__(256) kScore(int stage,
                                              const float* __restrict__ sb1,
                                              const float* __restrict__ sw2,
                                              const float* __restrict__ sb2) {
    __shared__ unsigned skeys[1536];
    __shared__ float    svals[1536];
    __shared__ TK tk;
    __shared__ int   ip[KEEP];
    __shared__ float cv[KEEP];
    __shared__ float b1c[32], w2c[32];
    const int g = blockIdx.x, tid = threadIdx.x;
    const int b = g & 15, chunk = g >> 4;
    const int kn = (chunk < 10) ? 6 : 5;
    const int k0 = (chunk < 10) ? chunk * 6 : 60 + (chunk - 10) * 5;
    const int l = stage + 1;
    const float* Wt = stage ? gWt1 : gWt0;
    if (tid < KEEP) {
        ip[tid] = gSelIdx[stage][b][tid];
        cv[tid] = gSelVal[stage][b][tid];
    }
    if (tid < 32) { b1c[tid] = sb1[tid]; w2c[tid] = sw2[tid]; }
    float Ureg[32];
    #pragma unroll
    for (int h = 0; h < 32; h++) Ureg[h] = gU[l][h][tid];
    __syncthreads();
    float b2 = sb2[0];
    for (int kk = 0; kk < kn; kk++) {
        int k = k0 + kk;
        float v = ftanh(Wt[ip[k] * 256 + tid] * cv[k]);        // coalesced gather
        float a = 0.f;
        #pragma unroll
        for (int h = 0; h < 32; h++) {
            float t = fmaf(v, Ureg[h], b1c[h]);
            a = fmaf(w2c[h], fmaxf(t, 0.f), a);
        }
        skeys[kk * 256 + tid] = fkey(a + b2);
        svals[kk * 256 + tid] = v;
    }
    __syncthreads();
    topk(skeys, kn * 256, &tk, tid, 256);
    if (tid < KEEP) {
        int j = tk.selI[tid];
        int slot = chunk * KEEP + tid;
        gPartK[stage][b][slot] = skeys[j];
        gPartI[stage][b][slot] = k0 * 256 + j;
        gPartV[stage][b][slot] = svals[j];
    }
}

// ========== k4: merge 1800 partials -> next stage's kept 100 (16 blocks, 512 thr) ==========
__global__ void __launch_bounds__(512) kMerge(int stage) {
    __shared__ unsigned skeys[MERGEW];
    __shared__ TK tk;
    const int b = blockIdx.x, tid = threadIdx.x;
    for (int idx = tid; idx < MERGEW; idx += 512) skeys[idx] = gPartK[stage][b][idx];
    __syncthreads();
    topk(skeys, MERGEW, &tk, tid, 512);
    if (tid < KEEP) {
        int j = tk.selI[tid];
        gSelIdx[stage + 1][b][tid] = gPartI[stage][b][j] & 255;
        gSelVal[stage + 1][b][tid] = gPartV[stage][b][j];
    }
}

// ========== k6: final merge + softmax + output (16 blocks, 512 thr) ==========
__global__ void __launch_bounds__(512) kFinal(float* __restrict__ out) {
    __shared__ unsigned skeys[MERGEW];
    __shared__ TK tk;
    __shared__ int   ipk[KEEP];
    __shared__ float wc[KEEP], selS[KEEP], red[4];
    const int b = blockIdx.x, tid = threadIdx.x;
    const int lane = tid & 31;
    for (int idx = tid; idx < MERGEW; idx += 512) skeys[idx] = gPartK[1][b][idx];
    __syncthreads();
    topk(skeys, MERGEW, &tk, tid, 512);
    if (tid < KEEP) {
        int j = tk.selI[tid];
        ipk[tid]  = gPartI[1][b][j] & 255;
        wc[tid]   = gPartV[1][b][j];             // value (no tanh after last layer)
        selS[tid] = ikey(skeys[j]);              // exact selection score
    }
    __syncthreads();
    float s = (tid < KEEP) ? selS[tid] : -INFINITY;
    if (tid < 128) {
        float m = s;
        #pragma unroll
        for (int o = 16; o; o >>= 1) m = fmaxf(m, __shfl_xor_sync(FULL, m, o));
        if (lane == 0) red[tid >> 5] = m;
    }
    __syncthreads();
    float mx = fmaxf(fmaxf(red[0], red[1]), fmaxf(red[2], red[3]));
    float e = (tid < KEEP) ? __expf(s - mx) : 0.f;
    __syncthreads();
    if (tid < 128) {
        float z = e;
        #pragma unroll
        for (int o = 16; o; o >>= 1) z += __shfl_xor_sync(FULL, z, o);
        if (lane == 0) red[tid >> 5] = z;
    }
    __syncthreads();
    float Z = red[0] + red[1] + red[2] + red[3];
    if (tid < KEEP) wc[tid] = wc[tid] * (e / Z);
    __syncthreads();
    if (tid < 128) {
        float acc = 0.f;
        #pragma unroll 4
        for (int q = 0; q < KEEP; q++)
            acc = fmaf(wc[q], gWt2[ipk[q] * 128 + tid], acc);   // coalesced
        out[b * 128 + tid] = acc;
    }
}

// ---------------------------------------------------------------------------------
extern "C" void kernel_launch(void* const* d_in, const int* in_sizes, int n_in,
                              void* d_out, int out_size) {
    const float *x, *W[3], *sw1[3], *sb1[3], *sw2[3], *sb2[3];
    x = (const float*)d_in[0];
    if (n_in >= 16 && in_sizes[2] == 65536) {
        for (int l = 0; l < 3; l++) W[l] = (const float*)d_in[1 + l];
        for (int l = 0; l < 3; l++) {
            int base = 4 + l * 4;
            sw1[l] = (const float*)d_in[base];     sb1[l] = (const float*)d_in[base + 1];
            sw2[l] = (const float*)d_in[base + 2]; sb2[l] = (const float*)d_in[base + 3];
        }
    } else {
        for (int l = 0; l < 3; l++) {
            int base = 1 + l * 5;
            W[l]   = (const float*)d_in[base];
            sw1[l] = (const float*)d_in[base + 1]; sb1[l] = (const float*)d_in[base + 2];
            sw2[l] = (const float*)d_in[base + 3]; sb2[l] = (const float*)d_in[base + 4];
        }
    }
    float* out = (float*)d_out;

    kPrep <<<64, 256>>>(W[0], W[1], W[2], sw1[0], sw1[1], sw1[2]);
    kSel0 <<<16, 256>>>(x, sb1[0], sw2[0], sb2[0]);
    kScore<<<288, 256>>>(0, sb1[1], sw2[1], sb2[1]);
    kMerge<<<16, 512>>>(0);
    kScore<<<288, 256>>>(1, sb1[2], sw2[2], sb2[2]);
    kFinal<<<16, 512>>>(out);
}

// round 8
// speedup vs baseline: 1.8200x; 1.0290x over previous
#include <cuda_runtime.h>
#include <math.h>

#define KEEP 100
#define NCHUNK 18
#define MERGEW 1800
#define FULL 0xFFFFFFFFu

// ---------------- device scratch (no allocations) ----------------
__device__ float    gU[3][32][256];          // U_l[h][i] = sum_o sw1[h,o]*W_l[o,i]
__device__ float    gWt0[256 * 256];         // gWt0[ip*256+i] = W0[i][ip]
__device__ float    gWt1[256 * 256];
__device__ float    gWt2[256 * 128];         // gWt2[i*128+j] = W2[j][i]
__device__ unsigned gPartK[2][16][MERGEW];   // per-chunk top-100 keys
__device__ int      gPartI[2][16][MERGEW];   // local candidate ids
__device__ float    gPartV[2][16][MERGEW];   // candidate values

struct TK {                                   // select scratch (shared)
    unsigned hist[256];
    int      selI[KEEP];
    int      eq[256];
    int      cnt[4];                          // 0:G 1:E 2:byte 3:newr
};

__device__ __forceinline__ unsigned fkey(float f) {
    unsigned u = __float_as_uint(f);
    return (u & 0x80000000u) ? ~u : (u | 0x80000000u);
}
__device__ __forceinline__ float ikey(unsigned k) {
    return __uint_as_float((k & 0x80000000u) ? (k & 0x7FFFFFFFu) : ~k);
}
__device__ __forceinline__ float ftanh(float x) {
    float e = __expf(2.f * x);
    return 1.f - __fdividef(2.f, e + 1.f);
}

// ---- exact top-KEEP radix select; selI[] = selected indices sorted ascending ----
template <int NT>
__device__ void topk(const unsigned* keys, int n, TK* t, int tid) {
    unsigned prefix = 0u;
    int r = KEEP;
    const int lane = tid & 31;
    const int nIter = (n + NT - 1) / NT;
    #pragma unroll
    for (int shift = 24; shift >= 0; shift -= 8) {
        if (tid < 256) t->hist[tid] = 0u;
        __syncthreads();
        unsigned pm = (shift == 24) ? 0u : (0xFFFFFFFFu << (shift + 8));
        for (int it = 0; it < nIter; it++) {
            int idx = it * NT + tid;
            unsigned k = (idx < n) ? keys[idx] : 0u;
            bool act = (idx < n) && ((k & pm) == prefix);
            unsigned bin = (k >> shift) & 255u;
            unsigned am = __ballot_sync(FULL, act);
            if (act) {
                unsigned peers = __match_any_sync(am, bin);
                if (lane == __ffs(peers) - 1) atomicAdd(&t->hist[bin], __popc(peers));
            }
        }
        __syncthreads();
        if (tid < 32) {                      // warp-0: suffix scan + threshold find
            int base = lane * 8;
            unsigned s[8]; unsigned run = 0u;
            #pragma unroll
            for (int j = 7; j >= 0; j--) { run += t->hist[base + j]; s[j] = run; }
            unsigned tt = run;
            #pragma unroll
            for (int off = 1; off < 32; off <<= 1) {
                unsigned uu = __shfl_down_sync(FULL, tt, off);
                if (lane + off < 32) tt += uu;
            }
            unsigned above = tt - run;
            unsigned cum0 = s[0] + above;
            unsigned nxt7 = __shfl_down_sync(FULL, cum0, 1);
            if (lane == 31) nxt7 = 0u;
            #pragma unroll
            for (int j = 0; j < 8; j++) {
                unsigned cj = s[j] + above;
                unsigned nj = (j < 7) ? (s[j + 1] + above) : nxt7;
                if (cj >= (unsigned)r && nj < (unsigned)r) {
                    t->cnt[2] = base + j;
                    t->cnt[3] = r - (int)nj;
                }
            }
        }
        __syncthreads();
        prefix |= ((unsigned)t->cnt[2]) << shift;
        r = t->cnt[3];
    }
    unsigned T = prefix;
    if (tid == 0) { t->cnt[0] = 0; t->cnt[1] = 0; }
    __syncthreads();
    for (int idx = tid; idx < n; idx += NT) {
        unsigned k = keys[idx];
        if (k > T)       { int pp = atomicAdd(&t->cnt[0], 1); t->selI[pp] = idx; }
        else if (k == T) { int pp = atomicAdd(&t->cnt[1], 1); if (pp < 256) t->eq[pp] = idx; }
    }
    __syncthreads();
    if (tid == 0) {                          // ties: smallest indices win
        int G = t->cnt[0], E = KEEP - G;
        int ne = t->cnt[1] < 256 ? t->cnt[1] : 256;
        for (int e = 0; e < E; e++) {
            int bmin = 0x7FFFFFFF, bp = 0;
            for (int q = 0; q < ne; q++) if (t->eq[q] < bmin) { bmin = t->eq[q]; bp = q; }
            t->selI[G + e] = bmin; t->eq[bp] = 0x7FFFFFFF;
        }
    }
    __syncthreads();
    int myIdx = 0, rank = 0;                 // deterministic: sort by index asc
    if (tid < KEEP) {
        myIdx = t->selI[tid];
        for (int q = 0; q < KEEP; q++) rank += (t->selI[q] < myIdx) ? 1 : 0;
    }
    __syncthreads();
    if (tid < KEEP) t->selI[rank] = myIdx;
    __syncthreads();
}

// ========== k1: U precompute (blocks 0-23) + W transposes (24-63) ==========
__global__ void __launch_bounds__(256) kPrep(const float* __restrict__ W0,
                                             const float* __restrict__ W1,
                                             const float* __restrict__ W2,
                                             const float* __restrict__ s10,
                                             const float* __restrict__ s11,
                                             const float* __restrict__ s12) {
    __shared__ float tile[64][65];
    const int tid = threadIdx.x, g = blockIdx.x;
    const int lane = tid & 31;
    if (g < 24) {
        int l = g >> 3, ic = g & 7;
        int ii = ic * 32 + lane;
        const float* W  = (l == 0) ? W0 : (l == 1) ? W1 : W2;
        const float* s1 = (l == 0) ? s10 : (l == 1) ? s11 : s12;
        int fo = (l == 2) ? 128 : 256;
        for (int hh = 0; hh < 4; hh++) {
            int h = (tid >> 5) + hh * 8;
            float acc = 0.f;
            for (int oc = 0; oc < fo; oc += 32) {
                float sv = s1[h * fo + oc + lane];
                #pragma unroll
                for (int j = 0; j < 32; j++) {
                    float svj = __shfl_sync(FULL, sv, j);
                    acc = fmaf(svj, W[(oc + j) * 256 + ii], acc);
                }
            }
            gU[l][h][ii] = acc;
        }
    } else {
        const float* src; float* dst; int t, srcld, dstld;
        if (g < 40)      { src = W0; dst = gWt0; t = g - 24; srcld = 256; dstld = 256; }
        else if (g < 56) { src = W1; dst = gWt1; t = g - 40; srcld = 256; dstld = 256; }
        else             { src = W2; dst = gWt2; t = g - 56; srcld = 256; dstld = 128; }
        int ncol = srcld >> 6;
        int tr = t / ncol, tc = t % ncol;
        for (int idx = tid; idx < 4096; idx += 256) {
            int r = idx >> 6, c = idx & 63;
            tile[r][c] = src[(tr * 64 + r) * srcld + tc * 64 + c];
        }
        __syncthreads();
        for (int idx = tid; idx < 4096; idx += 256) {
            int r = idx >> 6, c = idx & 63;
            dst[(tc * 64 + r) * dstld + tr * 64 + c] = tile[c][r];
        }
    }
}

// ========== k2: redundant select0 + stage-1 chunk scoring + local top (288 blocks) ==========
__global__ void __launch_bounds__(256) kScoreA(const float* __restrict__ x,
                                               const float* __restrict__ b10,
                                               const float* __restrict__ w20,
                                               const float* __restrict__ bb20,
                                               const float* __restrict__ b11,
                                               const float* __restrict__ w21,
                                               const float* __restrict__ bb21) {
    __shared__ unsigned skeys[1536];
    __shared__ float    svals[1536];
    __shared__ TK tk;
    __shared__ int   ip[KEEP];
    __shared__ float cv[KEEP];
    __shared__ float b1c[32], w2c[32];
    const int g = blockIdx.x, tid = threadIdx.x;
    const int b = g & 15, chunk = g >> 4;
    const int kn = (chunk < 10) ? 6 : 5;
    const int k0 = (chunk < 10) ? chunk * 6 : 60 + (chunk - 10) * 5;
    float Ureg[32];

    // --- redundant select0 over 256 layer-0 candidates ---
    if (tid < 32) { b1c[tid] = b10[tid]; w2c[tid] = w20[tid]; }
    #pragma unroll
    for (int h = 0; h < 32; h++) Ureg[h] = gU[0][h][tid];
    __syncthreads();
    float c0v = x[b * 256 + tid];
    float acc0 = 0.f;
    #pragma unroll
    for (int h = 0; h < 32; h++) {
        float t = fmaf(c0v, Ureg[h], b1c[h]);
        acc0 = fmaf(w2c[h], fmaxf(t, 0.f), acc0);
    }
    skeys[tid] = fkey(acc0 + bb20[0]);
    __syncthreads();
    topk<256>(skeys, 256, &tk, tid);
    if (tid < KEEP) {
        int i0 = tk.selI[tid];
        ip[tid] = i0;
        cv[tid] = x[b * 256 + i0];
    }

    // --- stage-1 chunk scoring ---
    if (tid < 32) { b1c[tid] = b11[tid]; w2c[tid] = w21[tid]; }
    #pragma unroll
    for (int h = 0; h < 32; h++) Ureg[h] = gU[1][h][tid];
    __syncthreads();
    float b2 = bb21[0];
    for (int kk = 0; kk < kn; kk++) {
        int k = k0 + kk;
        float v = ftanh(gWt0[ip[k] * 256 + tid] * cv[k]);      // coalesced gather
        float a = 0.f;
        #pragma unroll
        for (int h = 0; h < 32; h++) {
            float t = fmaf(v, Ureg[h], b1c[h]);
            a = fmaf(w2c[h], fmaxf(t, 0.f), a);
        }
        skeys[kk * 256 + tid] = fkey(a + b2);
        svals[kk * 256 + tid] = v;
    }
    __syncthreads();
    topk<256>(skeys, kn * 256, &tk, tid);
    if (tid < KEEP) {
        int j = tk.selI[tid];
        int slot = chunk * KEEP + tid;
        gPartK[0][b][slot] = skeys[j];
        gPartI[0][b][slot] = k0 * 256 + j;
        gPartV[0][b][slot] = svals[j];
    }
}

// ========== k3: redundant merge + stage-2 chunk scoring + local top (288 blocks) ==========
__global__ void __launch_bounds__(256) kScoreB(const float* __restrict__ b12,
                                               const float* __restrict__ w22,
                                               const float* __restrict__ bb22) {
    __shared__ unsigned skeys[MERGEW];        // merge then reuse for scoring (1536)
    __shared__ float    svals[1536];
    __shared__ TK tk;
    __shared__ int   ip[KEEP];
    __shared__ float cv[KEEP];
    __shared__ float b1c[32], w2c[32];
    const int g = blockIdx.x, tid = threadIdx.x;
    const int b = g & 15, chunk = g >> 4;
    const int kn = (chunk < 10) ? 6 : 5;
    const int k0 = (chunk < 10) ? chunk * 6 : 60 + (chunk - 10) * 5;
    float Ureg[32];

    // --- redundant merge of stage-1 partials ---
    for (int idx = tid; idx < MERGEW; idx += 256) skeys[idx] = gPartK[0][b][idx];
    if (tid < 32) { b1c[tid] = b12[tid]; w2c[tid] = w22[tid]; }
    #pragma unroll
    for (int h = 0; h < 32; h++) Ureg[h] = gU[2][h][tid];
    __syncthreads();
    topk<256>(skeys, MERGEW, &tk, tid);
    if (tid < KEEP) {
        int j = tk.selI[tid];
        ip[tid] = gPartI[0][b][j] & 255;
        cv[tid] = gPartV[0][b][j];
    }
    __syncthreads();

    // --- stage-2 chunk scoring ---
    float b2 = bb22[0];
    for (int kk = 0; kk < kn; kk++) {
        int k = k0 + kk;
        float v = ftanh(gWt1[ip[k] * 256 + tid] * cv[k]);
        float a = 0.f;
        #pragma unroll
        for (int h = 0; h < 32; h++) {
            float t = fmaf(v, Ureg[h], b1c[h]);
            a = fmaf(w2c[h], fmaxf(t, 0.f), a);
        }
        skeys[kk * 256 + tid] = fkey(a + b2);
        svals[kk * 256 + tid] = v;
    }
    __syncthreads();
    topk<256>(skeys, kn * 256, &tk, tid);
    if (tid < KEEP) {
        int j = tk.selI[tid];
        int slot = chunk * KEEP + tid;
        gPartK[1][b][slot] = skeys[j];
        gPartI[1][b][slot] = k0 * 256 + j;
        gPartV[1][b][slot] = svals[j];
    }
}

// ========== k4: final merge + softmax + output (16 blocks, 512 thr) ==========
__global__ void __launch_bounds__(512) kFinal(float* __restrict__ out) {
    __shared__ unsigned skeys[MERGEW];
    __shared__ TK tk;
    __shared__ int   ipk[KEEP];
    __shared__ float wc[KEEP], selS[KEEP], red[4];
    const int b = blockIdx.x, tid = threadIdx.x;
    const int lane = tid & 31;
    for (int idx = tid; idx < MERGEW; idx += 512) skeys[idx] = gPartK[1][b][idx];
    __syncthreads();
    topk<512>(skeys, MERGEW, &tk, tid);
    if (tid < KEEP) {
        int j = tk.selI[tid];
        ipk[tid]  = gPartI[1][b][j] & 255;
        wc[tid]   = gPartV[1][b][j];             // value (no tanh after last layer)
        selS[tid] = ikey(skeys[j]);              // exact selection score
    }
    __syncthreads();
    float s = (tid < KEEP) ? selS[tid] : -INFINITY;
    if (tid < 128) {
        float m = s;
        #pragma unroll
        for (int o = 16; o; o >>= 1) m = fmaxf(m, __shfl_xor_sync(FULL, m, o));
        if (lane == 0) red[tid >> 5] = m;
    }
    __syncthreads();
    float mx = fmaxf(fmaxf(red[0], red[1]), fmaxf(red[2], red[3]));
    float e = (tid < KEEP) ? __expf(s - mx) : 0.f;
    __syncthreads();
    if (tid < 128) {
        float z = e;
        #pragma unroll
        for (int o = 16; o; o >>= 1) z += __shfl_xor_sync(FULL, z, o);
        if (lane == 0) red[tid >> 5] = z;
    }
    __syncthreads();
    float Z = red[0] + red[1] + red[2] + red[3];
    if (tid < KEEP) wc[tid] = wc[tid] * (e / Z);
    __syncthreads();
    if (tid < 128) {
        float acc = 0.f;
        #pragma unroll 4
        for (int q = 0; q < KEEP; q++)
            acc = fmaf(wc[q], gWt2[ipk[q] * 128 + tid], acc);   // coalesced
        out[b * 128 + tid] = acc;
    }
}

// ---------------------------------------------------------------------------------
extern "C" void kernel_launch(void* const* d_in, const int* in_sizes, int n_in,
                              void* d_out, int out_size) {
    const float *x, *W[3], *sw1[3], *sb1[3], *sw2[3], *sb2[3];
    x = (const float*)d_in[0];
    if (n_in >= 16 && in_sizes[2] == 65536) {
        for (int l = 0; l < 3; l++) W[l] = (const float*)d_in[1 + l];
        for (int l = 0; l < 3; l++) {
            int base = 4 + l * 4;
            sw1[l] = (const float*)d_in[base];     sb1[l] = (const float*)d_in[base + 1];
            sw2[l] = (const float*)d_in[base + 2]; sb2[l] = (const float*)d_in[base + 3];
        }
    } else {
        for (int l = 0; l < 3; l++) {
            int base = 1 + l * 5;
            W[l]   = (const float*)d_in[base];
            sw1[l] = (const float*)d_in[base + 1]; sb1[l] = (const float*)d_in[base + 2];
            sw2[l] = (const float*)d_in[base + 3]; sb2[l] = (const float*)d_in[base + 4];
        }
    }
    float* out = (float*)d_out;

    kPrep  <<<64, 256>>>(W[0], W[1], W[2], sw1[0], sw1[1], sw1[2]);
    kScoreA<<<288, 256>>>(x, sb1[0], sw2[0], sb2[0], sb1[1], sw2[1], sb2[1]);
    kScoreB<<<288, 256>>>(sb1[2], sw2[2], sb2[2]);
    kFinal <<<16, 512>>>(out);
}